// round 9
// baseline (speedup 1.0000x reference)
#include <cuda_runtime.h>
#include <cuda_bf16.h>
#include <math.h>

// ---------------------------------------------------------------------------
// StandardPartitionAttention  (Swin-style window attention, DEPTH=2)
// B=4, C=256, H=W=128, WS=8 -> n=64 tokens/window, nW=1024, TOK=65536
// D=256, HEADS=8, DH=32, INNER=256, MLP=1024
// Output: [4,256,128,128] (16777216 f32)  ++  attns [2,1024,8,64,64] (67108864 f32)
// R8: all GEMMs moved to tf32 tensor cores (mma.sync.m16n8k8).
// ---------------------------------------------------------------------------

#define TOK 65536
#define Dm  256
#define NWIN 1024

// scratch (device globals: allocation-free)
__device__ float g_t  [TOK * 256];    // residual stream
__device__ float g_h  [TOK * 256];    // LN output / gathered input
__device__ float g_qkv[TOK * 768];
__device__ float g_o  [TOK * 256];
__device__ float g_mlp[TOK * 1024];
__device__ float g_bp [2 * 8 * 64 * 64];   // bias + 0.01*gaussian, per layer/head

// ---------------------------------------------------------------------------
// window partition gather:  x[B,C,H,W] -> xg[token, C]
// ---------------------------------------------------------------------------
__global__ void gather_kernel(const float* __restrict__ x, float* __restrict__ xg)
{
    __shared__ float s[32][33];
    int bh = blockIdx.z; int b = bh >> 7; int h = bh & 127;
    int w0 = blockIdx.x * 32, c0 = blockIdx.y * 32;
    int tx = threadIdx.x, ty = threadIdx.y;
#pragma unroll
    for (int i = 0; i < 4; i++) {
        int ch = c0 + ty + i * 8;
        s[ty + i * 8][tx] = x[(((size_t)b * 256 + ch) * 128 + h) * 128 + w0 + tx];
    }
    __syncthreads();
    int wh = h >> 3, r = h & 7;
#pragma unroll
    for (int i = 0; i < 4; i++) {
        int w = w0 + ty + i * 8;
        int row = ((b * 16 + wh) * 16 + (w >> 3)) * 64 + r * 8 + (w & 7);
        xg[(size_t)row * 256 + c0 + tx] = s[tx][ty + i * 8];
    }
}

// window reverse: t[token, D] -> out[B, D, H, W]
__global__ void reverse_kernel(const float* __restrict__ t, float* __restrict__ out)
{
    __shared__ float s[32][33];
    int bh = blockIdx.z; int b = bh >> 7; int h = bh & 127;
    int w0 = blockIdx.x * 32, d0 = blockIdx.y * 32;
    int tx = threadIdx.x, ty = threadIdx.y;
    int wh = h >> 3, r = h & 7;
#pragma unroll
    for (int i = 0; i < 4; i++) {
        int w = w0 + ty + i * 8;
        int row = ((b * 16 + wh) * 16 + (w >> 3)) * 64 + r * 8 + (w & 7);
        s[ty + i * 8][tx] = t[(size_t)row * 256 + d0 + tx];
    }
    __syncthreads();
#pragma unroll
    for (int i = 0; i < 4; i++) {
        int d = d0 + ty + i * 8;
        out[(((size_t)b * 256 + d) * 128 + h) * 128 + w0 + tx] = s[tx][ty + i * 8];
    }
}

// ---------------------------------------------------------------------------
// tf32 tensor-core GEMM: C[M,N] = A[M,K] @ B[K,N] (+bias) (+relu) (+resid)
// 128x128 block, BK=16, 256 threads (2x4 warps, 64x32 warp tile).
// mma.sync.m16n8k8.tf32 ; smem stride 136 -> conflict-free fragment loads.
// M,N multiples of 128; K multiple of 16.
// ---------------------------------------------------------------------------
__device__ __forceinline__ unsigned f2tf(float f)
{
    unsigned u;
    asm("cvt.rna.tf32.f32 %0, %1;" : "=r"(u) : "f"(f));
    return u;
}

__device__ __forceinline__ void mma_tf32(float* c, const unsigned* a,
                                         unsigned b0, unsigned b1)
{
    asm volatile(
        "mma.sync.aligned.m16n8k8.row.col.f32.tf32.tf32.f32 "
        "{%0,%1,%2,%3}, {%4,%5,%6,%7}, {%8,%9}, {%0,%1,%2,%3};"
        : "+f"(c[0]), "+f"(c[1]), "+f"(c[2]), "+f"(c[3])
        : "r"(a[0]), "r"(a[1]), "r"(a[2]), "r"(a[3]), "r"(b0), "r"(b1));
}

template<bool HAS_BIAS, bool RELU, bool RES>
__global__ void __launch_bounds__(256, 2)
tgemm_kernel(const float* __restrict__ A, const float* __restrict__ B,
             const float* __restrict__ bias, const float* __restrict__ resid,
             float* __restrict__ C, int M, int N, int K)
{
    __shared__ unsigned As[16][136];   // [k][m], stride 136 -> (8k+m)%32 conflict-free
    __shared__ unsigned Bs[16][136];   // [k][n]

    int tid  = threadIdx.x;
    int warp = tid >> 5, lane = tid & 31;
    int wm = warp >> 2, wn = warp & 3;     // 2x4 warp grid
    int g  = lane >> 2, tg = lane & 3;     // groupID / threadID-in-group
    int bm = blockIdx.y * 128, bn = blockIdx.x * 128;

    float acc[4][4][4];
#pragma unroll
    for (int mt = 0; mt < 4; mt++)
#pragma unroll
        for (int nt = 0; nt < 4; nt++)
#pragma unroll
            for (int q = 0; q < 4; q++) acc[mt][nt][q] = 0.f;

    // staging: A tile 128x16 (2 float4/thread), B tile 16x128 (2 float4/thread)
    int arow = tid >> 2;       // 0..63 ; second load at +64
    int ac4  = tid & 3;
    int brow = tid >> 5;       // 0..7  ; second load at +8
    int bc4  = tid & 31;

    const float* Aptr  = A + (size_t)(bm + arow) * K + ac4 * 4;
    const float* Aptr2 = Aptr + (size_t)64 * K;
    const float* Bptr  = B + (size_t)brow * N + bn + bc4 * 4;
    const float* Bptr2 = Bptr + (size_t)8 * N;

    float4 av0 = *(const float4*)Aptr;
    float4 av1 = *(const float4*)Aptr2;
    float4 bv0 = *(const float4*)Bptr;
    float4 bv1 = *(const float4*)Bptr2;

    for (int k0 = 0; k0 < K; k0 += 16) {
        // store staged tiles (A transposed into [k][m])
        As[ac4 * 4 + 0][arow]      = f2tf(av0.x);
        As[ac4 * 4 + 1][arow]      = f2tf(av0.y);
        As[ac4 * 4 + 2][arow]      = f2tf(av0.z);
        As[ac4 * 4 + 3][arow]      = f2tf(av0.w);
        As[ac4 * 4 + 0][arow + 64] = f2tf(av1.x);
        As[ac4 * 4 + 1][arow + 64] = f2tf(av1.y);
        As[ac4 * 4 + 2][arow + 64] = f2tf(av1.z);
        As[ac4 * 4 + 3][arow + 64] = f2tf(av1.w);
        {
            uint4 u0 = make_uint4(f2tf(bv0.x), f2tf(bv0.y), f2tf(bv0.z), f2tf(bv0.w));
            uint4 u1 = make_uint4(f2tf(bv1.x), f2tf(bv1.y), f2tf(bv1.z), f2tf(bv1.w));
            *(uint4*)(&Bs[brow][bc4 * 4])     = u0;
            *(uint4*)(&Bs[brow + 8][bc4 * 4]) = u1;
        }
        __syncthreads();

        // prefetch next chunk while computing this one
        if (k0 + 16 < K) {
            Aptr += 16; Aptr2 += 16;
            Bptr += (size_t)16 * N; Bptr2 += (size_t)16 * N;
            av0 = *(const float4*)Aptr;
            av1 = *(const float4*)Aptr2;
            bv0 = *(const float4*)Bptr;
            bv1 = *(const float4*)Bptr2;
        }

#pragma unroll
        for (int ks = 0; ks < 2; ks++) {
            int kk = ks * 8;
            unsigned af[4][4];
#pragma unroll
            for (int mt = 0; mt < 4; mt++) {
                int m = wm * 64 + mt * 16;
                af[mt][0] = As[kk + tg][m + g];
                af[mt][1] = As[kk + tg][m + g + 8];
                af[mt][2] = As[kk + tg + 4][m + g];
                af[mt][3] = As[kk + tg + 4][m + g + 8];
            }
#pragma unroll
            for (int nt = 0; nt < 4; nt++) {
                int n = wn * 32 + nt * 8 + g;
                unsigned b0 = Bs[kk + tg][n];
                unsigned b1 = Bs[kk + tg + 4][n];
#pragma unroll
                for (int mt = 0; mt < 4; mt++)
                    mma_tf32(acc[mt][nt], af[mt], b0, b1);
            }
        }
        __syncthreads();
    }

    // epilogue: c0/c1 adjacent columns -> float2 stores
#pragma unroll
    for (int mt = 0; mt < 4; mt++) {
#pragma unroll
        for (int nt = 0; nt < 4; nt++) {
            int row0 = bm + wm * 64 + mt * 16 + g;
            int col0 = bn + wn * 32 + nt * 8 + tg * 2;
#pragma unroll
            for (int half = 0; half < 2; half++) {
                int row = row0 + half * 8;
                float v0 = acc[mt][nt][half * 2 + 0];
                float v1 = acc[mt][nt][half * 2 + 1];
                if (HAS_BIAS) { v0 += bias[col0]; v1 += bias[col0 + 1]; }
                if (RELU)     { v0 = fmaxf(v0, 0.f); v1 = fmaxf(v1, 0.f); }
                if (RES) {
                    const float2 r = *(const float2*)(resid + (size_t)row * N + col0);
                    v0 += r.x; v1 += r.y;
                }
                *(float2*)(C + (size_t)row * N + col0) = make_float2(v0, v1);
            }
        }
    }
}

// ---------------------------------------------------------------------------
// LayerNorm: one warp per row of 256
// ---------------------------------------------------------------------------
__global__ void ln_kernel(const float* __restrict__ x, const float* __restrict__ g,
                          const float* __restrict__ b, float* __restrict__ y)
{
    int row  = blockIdx.x * 8 + threadIdx.y;
    int lane = threadIdx.x;
    const float* xr = x + (size_t)row * 256;
    float v[8]; float s = 0.f, s2 = 0.f;
#pragma unroll
    for (int i = 0; i < 8; i++) {
        v[i] = xr[lane + i * 32];
        s  += v[i];
        s2 += v[i] * v[i];
    }
#pragma unroll
    for (int o = 16; o; o >>= 1) {
        s  += __shfl_xor_sync(0xffffffffu, s,  o);
        s2 += __shfl_xor_sync(0xffffffffu, s2, o);
    }
    float mean = s * (1.f / 256.f);
    float var  = s2 * (1.f / 256.f) - mean * mean;
    float inv  = rsqrtf(var + 1e-5f);
#pragma unroll
    for (int i = 0; i < 8; i++) {
        int c = lane + i * 32;
        y[(size_t)row * 256 + c] = (v[i] - mean) * inv * g[c] + b[c];
    }
}

// ---------------------------------------------------------------------------
// precompute bias + 0.01 * gaussian decay per (layer, head): g_bp
// ---------------------------------------------------------------------------
__global__ void bp_kernel(const float* __restrict__ bias_table,
                          const float* __restrict__ headsita)
{
    int l = blockIdx.y, head = blockIdx.x;
    int i = threadIdx.x;
    float sita   = headsita[l * 8 + head];
    float factor = 1.0f / (2.0f * sita * sita + 1e-10f);
    int ih = i >> 3, iw = i & 7;
    for (int j = 0; j < 64; j++) {
        int jh = j >> 3, jw = j & 7;
        int dh = ih - jh, dw = iw - jw;
        float fh = (float)dh * 0.125f, fw = (float)dw * 0.125f;
        float dis = fh * fh + fw * fw;
        int rpi = (dh + 7) * 15 + (dw + 7);
        float bv = bias_table[((size_t)l * 225 + rpi) * 8 + head];
        g_bp[(((size_t)l * 8 + head) * 64 + i) * 64 + j] = bv + 0.01f * expf(-factor * dis);
    }
}

// ---------------------------------------------------------------------------
// attention per (window, head): 64 threads, thread i owns query row i.
// ---------------------------------------------------------------------------
__global__ void __launch_bounds__(64)
attn_kernel(const float* __restrict__ qkv, float* __restrict__ attns_out,
            float* __restrict__ obuf, int layer)
{
    const float SCALE = 0.17677669529663689f;  // 32^-0.5
    int head = blockIdx.x;
    int win  = blockIdx.y;
    int i    = threadIdx.x;

    __shared__ float ks[64][32];
    __shared__ float vs[64][32];

    const float* base = qkv + (size_t)win * 64 * 768 + head * 32;
    float q[32];
#pragma unroll
    for (int d = 0; d < 32; d++) q[d]      = base[(size_t)i * 768 + d];
#pragma unroll
    for (int d = 0; d < 32; d++) ks[i][d]  = base[(size_t)i * 768 + 256 + d];
#pragma unroll
    for (int d = 0; d < 32; d++) vs[i][d]  = base[(size_t)i * 768 + 512 + d];
    __syncthreads();

    float dots[64];
#pragma unroll 4
    for (int j = 0; j < 64; j++) {
        float s = 0.f;
#pragma unroll
        for (int d = 0; d < 32; d++) s += q[d] * ks[j][d];
        dots[j] = s * SCALE;
    }

    // softmax over raw dots (attns output)
    float m0 = -1e30f;
#pragma unroll
    for (int j = 0; j < 64; j++) m0 = fmaxf(m0, dots[j]);
    float sum0 = 0.f;
#pragma unroll
    for (int j = 0; j < 64; j++) sum0 += expf(dots[j] - m0);
    float inv0 = 1.f / sum0;
    float* arow = attns_out + (((size_t)layer * NWIN + win) * 8 + head) * 4096 + (size_t)i * 64;
#pragma unroll
    for (int j = 0; j < 64; j++) arow[j] = expf(dots[j] - m0) * inv0;

    // biased softmax
    const float* bp = g_bp + (((size_t)layer * 8 + head) * 64 + i) * 64;
#pragma unroll
    for (int j = 0; j < 64; j++) dots[j] += bp[j];
    float m1 = -1e30f;
#pragma unroll
    for (int j = 0; j < 64; j++) m1 = fmaxf(m1, dots[j]);
    float sum1 = 0.f;
#pragma unroll
    for (int j = 0; j < 64; j++) { dots[j] = expf(dots[j] - m1); sum1 += dots[j]; }
    float inv1 = 1.f / sum1;

    float acc[32];
#pragma unroll
    for (int d = 0; d < 32; d++) acc[d] = 0.f;
#pragma unroll 4
    for (int j = 0; j < 64; j++) {
        float a = dots[j] * inv1;
#pragma unroll
        for (int d = 0; d < 32; d++) acc[d] += a * vs[j][d];
    }
    float* orow = obuf + (size_t)(win * 64 + i) * 256 + head * 32;
#pragma unroll
    for (int d = 0; d < 32; d++) orow[d] = acc[d];
}

// ---------------------------------------------------------------------------
extern "C" void kernel_launch(void* const* d_in, const int* in_sizes, int n_in,
                              void* d_out, int out_size)
{
    const float* x          = (const float*)d_in[0];
    const float* W_patch    = (const float*)d_in[1];
    const float* b_patch    = (const float*)d_in[2];
    const float* ln1_g      = (const float*)d_in[3];
    const float* ln1_b      = (const float*)d_in[4];
    const float* Wqkv       = (const float*)d_in[5];
    const float* headsita   = (const float*)d_in[6];
    const float* bias_table = (const float*)d_in[7];
    const float* Wout       = (const float*)d_in[8];
    const float* bout       = (const float*)d_in[9];
    const float* ln2_g      = (const float*)d_in[10];
    const float* ln2_b      = (const float*)d_in[11];
    const float* W1         = (const float*)d_in[12];
    const float* b1         = (const float*)d_in[13];
    const float* W2         = (const float*)d_in[14];
    const float* b2         = (const float*)d_in[15];

    float* out   = (float*)d_out;
    float* attns = out + (size_t)16777216;

    float *t, *h, *qkvb, *ob, *mlpb;
    cudaGetSymbolAddress((void**)&t,    g_t);
    cudaGetSymbolAddress((void**)&h,    g_h);
    cudaGetSymbolAddress((void**)&qkvb, g_qkv);
    cudaGetSymbolAddress((void**)&ob,   g_o);
    cudaGetSymbolAddress((void**)&mlpb, g_mlp);

    dim3 tb32x8(32, 8);
    dim3 g_gather(4, 8, 512);

    // 1. window partition gather -> h
    gather_kernel<<<g_gather, tb32x8>>>(x, h);

    // 2. patch embed: t = h @ W_patch + b_patch
    tgemm_kernel<true, false, false><<<dim3(2, 512), 256>>>(h, W_patch, b_patch, nullptr, t, TOK, 256, 256);

    // 3. bias+pos tables for both layers
    bp_kernel<<<dim3(8, 2), 64>>>(bias_table, headsita);

    for (int l = 0; l < 2; l++) {
        // LN1 -> h
        ln_kernel<<<8192, tb32x8>>>(t, ln1_g + l * 256, ln1_b + l * 256, h);
        // qkv = h @ Wqkv[l]
        tgemm_kernel<false, false, false><<<dim3(6, 512), 256>>>(h, Wqkv + (size_t)l * 196608, nullptr, nullptr, qkvb, TOK, 768, 256);
        // attention
        attn_kernel<<<dim3(8, NWIN), 64>>>(qkvb, attns, ob, l);
        // t = o @ Wout[l] + bout[l] + t
        tgemm_kernel<true, false, true><<<dim3(2, 512), 256>>>(ob, Wout + (size_t)l * 65536, bout + l * 256, t, t, TOK, 256, 256);
        // LN2 -> h
        ln_kernel<<<8192, tb32x8>>>(t, ln2_g + l * 256, ln2_b + l * 256, h);
        // mlp = relu(h @ W1[l] + b1[l])
        tgemm_kernel<true, true, false><<<dim3(8, 512), 256>>>(h, W1 + (size_t)l * 262144, b1 + l * 1024, nullptr, mlpb, TOK, 1024, 256);
        // t = mlp @ W2[l] + b2[l] + t
        tgemm_kernel<true, false, true><<<dim3(2, 512), 256>>>(mlpb, W2 + (size_t)l * 262144, b2 + l * 256, t, t, TOK, 256, 1024);
    }

    // window reverse -> out
    reverse_kernel<<<g_gather, tb32x8>>>(t, out);
}

// round 10
// speedup vs baseline: 1.1057x; 1.1057x over previous
#include <cuda_runtime.h>
#include <cuda_bf16.h>
#include <math.h>

// ---------------------------------------------------------------------------
// StandardPartitionAttention  (Swin-style window attention, DEPTH=2)
// B=4, C=256, H=W=128, WS=8 -> n=64 tokens/window, nW=1024, TOK=65536
// D=256, HEADS=8, DH=32, INNER=256, MLP=1024
// R10: GEMM mainloop -> 4-stage cp.async pipeline (tf32 cvt at fragment load).
// ---------------------------------------------------------------------------

#define TOK 65536
#define NWIN 1024

// scratch (device globals: allocation-free)
__device__ float g_t  [TOK * 256];
__device__ float g_h  [TOK * 256];
__device__ float g_qkv[TOK * 768];
__device__ float g_o  [TOK * 256];
__device__ float g_mlp[TOK * 1024];
__device__ float g_bp [2 * 8 * 64 * 64];

// ---------------------------------------------------------------------------
// window partition gather:  x[B,C,H,W] -> xg[token, C]
// ---------------------------------------------------------------------------
__global__ void gather_kernel(const float* __restrict__ x, float* __restrict__ xg)
{
    __shared__ float s[32][33];
    int bh = blockIdx.z; int b = bh >> 7; int h = bh & 127;
    int w0 = blockIdx.x * 32, c0 = blockIdx.y * 32;
    int tx = threadIdx.x, ty = threadIdx.y;
#pragma unroll
    for (int i = 0; i < 4; i++) {
        int ch = c0 + ty + i * 8;
        s[ty + i * 8][tx] = x[(((size_t)b * 256 + ch) * 128 + h) * 128 + w0 + tx];
    }
    __syncthreads();
    int wh = h >> 3, r = h & 7;
#pragma unroll
    for (int i = 0; i < 4; i++) {
        int w = w0 + ty + i * 8;
        int row = ((b * 16 + wh) * 16 + (w >> 3)) * 64 + r * 8 + (w & 7);
        xg[(size_t)row * 256 + c0 + tx] = s[tx][ty + i * 8];
    }
}

__global__ void reverse_kernel(const float* __restrict__ t, float* __restrict__ out)
{
    __shared__ float s[32][33];
    int bh = blockIdx.z; int b = bh >> 7; int h = bh & 127;
    int w0 = blockIdx.x * 32, d0 = blockIdx.y * 32;
    int tx = threadIdx.x, ty = threadIdx.y;
    int wh = h >> 3, r = h & 7;
#pragma unroll
    for (int i = 0; i < 4; i++) {
        int w = w0 + ty + i * 8;
        int row = ((b * 16 + wh) * 16 + (w >> 3)) * 64 + r * 8 + (w & 7);
        s[ty + i * 8][tx] = t[(size_t)row * 256 + d0 + tx];
    }
    __syncthreads();
#pragma unroll
    for (int i = 0; i < 4; i++) {
        int d = d0 + ty + i * 8;
        out[(((size_t)b * 256 + d) * 128 + h) * 128 + w0 + tx] = s[tx][ty + i * 8];
    }
}

// ---------------------------------------------------------------------------
// tf32 tensor-core GEMM, 4-stage cp.async pipeline.
// C[M,N] = A[M,K] @ B[K,N] (+bias) (+relu) (+resid)
// 128x128 block, BK=16, 256 threads (2x4 warps, 64x32 warp tile).
// A smem [m][k] stride 20 (conflict-free frag LDS), B smem [k][n] stride 136.
// ---------------------------------------------------------------------------
#define STAGES 4
#define AS_STRIDE 20
#define BS_STRIDE 136
#define AS_SIZE (128 * AS_STRIDE)      // floats per stage
#define BS_SIZE (16 * BS_STRIDE)
#define GEMM_SMEM_BYTES (STAGES * (AS_SIZE + BS_SIZE) * 4)

__device__ __forceinline__ unsigned f2tf(float f)
{
    unsigned u;
    asm("cvt.rna.tf32.f32 %0, %1;" : "=r"(u) : "f"(f));
    return u;
}

__device__ __forceinline__ void cp16(float* dst, const float* src)
{
    unsigned d = (unsigned)__cvta_generic_to_shared(dst);
    asm volatile("cp.async.cg.shared.global [%0], [%1], 16;" :: "r"(d), "l"(src));
}

__device__ __forceinline__ void mma_tf32(float* c, const unsigned* a,
                                         unsigned b0, unsigned b1)
{
    asm volatile(
        "mma.sync.aligned.m16n8k8.row.col.f32.tf32.tf32.f32 "
        "{%0,%1,%2,%3}, {%4,%5,%6,%7}, {%8,%9}, {%0,%1,%2,%3};"
        : "+f"(c[0]), "+f"(c[1]), "+f"(c[2]), "+f"(c[3])
        : "r"(a[0]), "r"(a[1]), "r"(a[2]), "r"(a[3]), "r"(b0), "r"(b1));
}

template<bool HAS_BIAS, bool RELU, bool RES>
__global__ void __launch_bounds__(256)
tgemm_kernel(const float* __restrict__ A, const float* __restrict__ B,
             const float* __restrict__ bias, const float* __restrict__ resid,
             float* __restrict__ C, int M, int N, int K)
{
    extern __shared__ float sm[];
    float* As = sm;                        // [STAGES][128][20]
    float* Bs = sm + STAGES * AS_SIZE;     // [STAGES][16][136]

    int tid  = threadIdx.x;
    int warp = tid >> 5, lane = tid & 31;
    int wm = warp >> 2, wn = warp & 3;     // 2x4 warp grid
    int g  = lane >> 2, tg = lane & 3;
    int bm = blockIdx.y * 128, bn = blockIdx.x * 128;

    float acc[4][4][4];
#pragma unroll
    for (int mt = 0; mt < 4; mt++)
#pragma unroll
        for (int nt = 0; nt < 4; nt++)
#pragma unroll
            for (int q = 0; q < 4; q++) acc[mt][nt][q] = 0.f;

    // staging assignment: A 128 rows x 64B (2 chunks/thread), B 16 rows x 512B
    int arow = tid >> 2, ac4 = tid & 3;    // arow 0..63, +64 second
    int brow = tid >> 5, bc4 = tid & 31;   // brow 0..7,  +8 second

    const float* Abase = A + (size_t)(bm + arow) * K + ac4 * 4;
    const float* Bbase = B + (size_t)brow * N + bn + bc4 * 4;

    int nt_tiles = K >> 4;

    // prologue: issue STAGES-1 tiles
#pragma unroll
    for (int pt = 0; pt < STAGES - 1; pt++) {
        const float* a0 = Abase + pt * 16;
        const float* b0 = Bbase + (size_t)(pt * 16) * N;
        float* as = As + pt * AS_SIZE;
        float* bs = Bs + pt * BS_SIZE;
        cp16(as + arow * AS_STRIDE + ac4 * 4, a0);
        cp16(as + (arow + 64) * AS_STRIDE + ac4 * 4, a0 + (size_t)64 * K);
        cp16(bs + brow * BS_STRIDE + bc4 * 4, b0);
        cp16(bs + (brow + 8) * BS_STRIDE + bc4 * 4, b0 + (size_t)8 * N);
        asm volatile("cp.async.commit_group;");
    }

    for (int i = 0; i < nt_tiles; i++) {
        // issue tile i+STAGES-1
        int it = i + STAGES - 1;
        if (it < nt_tiles) {
            int s = it % STAGES;
            const float* a0 = Abase + it * 16;
            const float* b0 = Bbase + (size_t)(it * 16) * N;
            float* as = As + s * AS_SIZE;
            float* bs = Bs + s * BS_SIZE;
            cp16(as + arow * AS_STRIDE + ac4 * 4, a0);
            cp16(as + (arow + 64) * AS_STRIDE + ac4 * 4, a0 + (size_t)64 * K);
            cp16(bs + brow * BS_STRIDE + bc4 * 4, b0);
            cp16(bs + (brow + 8) * BS_STRIDE + bc4 * 4, b0 + (size_t)8 * N);
        }
        asm volatile("cp.async.commit_group;");
        asm volatile("cp.async.wait_group %0;" :: "n"(STAGES - 1));
        __syncthreads();

        const float* as = As + (i % STAGES) * AS_SIZE;
        const float* bs = Bs + (i % STAGES) * BS_SIZE;

#pragma unroll
        for (int ks = 0; ks < 2; ks++) {
            int kk = ks * 8;
            unsigned af[4][4];
#pragma unroll
            for (int mt = 0; mt < 4; mt++) {
                int m = wm * 64 + mt * 16;
                af[mt][0] = f2tf(as[(m + g)     * AS_STRIDE + kk + tg]);
                af[mt][1] = f2tf(as[(m + g + 8) * AS_STRIDE + kk + tg]);
                af[mt][2] = f2tf(as[(m + g)     * AS_STRIDE + kk + tg + 4]);
                af[mt][3] = f2tf(as[(m + g + 8) * AS_STRIDE + kk + tg + 4]);
            }
#pragma unroll
            for (int nt = 0; nt < 4; nt++) {
                int n = wn * 32 + nt * 8 + g;
                unsigned b0 = f2tf(bs[(kk + tg)     * BS_STRIDE + n]);
                unsigned b1 = f2tf(bs[(kk + tg + 4) * BS_STRIDE + n]);
#pragma unroll
                for (int mt = 0; mt < 4; mt++)
                    mma_tf32(acc[mt][nt], af[mt], b0, b1);
            }
        }
        __syncthreads();   // guard stage reuse by next iteration's cp.async
    }

    // epilogue
#pragma unroll
    for (int mt = 0; mt < 4; mt++) {
#pragma unroll
        for (int nt = 0; nt < 4; nt++) {
            int row0 = bm + wm * 64 + mt * 16 + g;
            int col0 = bn + wn * 32 + nt * 8 + tg * 2;
#pragma unroll
            for (int half = 0; half < 2; half++) {
                int row = row0 + half * 8;
                float v0 = acc[mt][nt][half * 2 + 0];
                float v1 = acc[mt][nt][half * 2 + 1];
                if (HAS_BIAS) { v0 += bias[col0]; v1 += bias[col0 + 1]; }
                if (RELU)     { v0 = fmaxf(v0, 0.f); v1 = fmaxf(v1, 0.f); }
                if (RES) {
                    const float2 r = *(const float2*)(resid + (size_t)row * N + col0);
                    v0 += r.x; v1 += r.y;
                }
                *(float2*)(C + (size_t)row * N + col0) = make_float2(v0, v1);
            }
        }
    }
}

// ---------------------------------------------------------------------------
// LayerNorm: one warp per row of 256
// ---------------------------------------------------------------------------
__global__ void ln_kernel(const float* __restrict__ x, const float* __restrict__ g,
                          const float* __restrict__ b, float* __restrict__ y)
{
    int row  = blockIdx.x * 8 + threadIdx.y;
    int lane = threadIdx.x;
    const float* xr = x + (size_t)row * 256;
    float v[8]; float s = 0.f, s2 = 0.f;
#pragma unroll
    for (int i = 0; i < 8; i++) {
        v[i] = xr[lane + i * 32];
        s  += v[i];
        s2 += v[i] * v[i];
    }
#pragma unroll
    for (int o = 16; o; o >>= 1) {
        s  += __shfl_xor_sync(0xffffffffu, s,  o);
        s2 += __shfl_xor_sync(0xffffffffu, s2, o);
    }
    float mean = s * (1.f / 256.f);
    float var  = s2 * (1.f / 256.f) - mean * mean;
    float inv  = rsqrtf(var + 1e-5f);
#pragma unroll
    for (int i = 0; i < 8; i++) {
        int c = lane + i * 32;
        y[(size_t)row * 256 + c] = (v[i] - mean) * inv * g[c] + b[c];
    }
}

// ---------------------------------------------------------------------------
// precompute bias + 0.01 * gaussian decay per (layer, head): g_bp
// ---------------------------------------------------------------------------
__global__ void bp_kernel(const float* __restrict__ bias_table,
                          const float* __restrict__ headsita)
{
    int l = blockIdx.y, head = blockIdx.x;
    int i = threadIdx.x;
    float sita   = headsita[l * 8 + head];
    float factor = 1.0f / (2.0f * sita * sita + 1e-10f);
    int ih = i >> 3, iw = i & 7;
    for (int j = 0; j < 64; j++) {
        int jh = j >> 3, jw = j & 7;
        int dh = ih - jh, dw = iw - jw;
        float fh = (float)dh * 0.125f, fw = (float)dw * 0.125f;
        float dis = fh * fh + fw * fw;
        int rpi = (dh + 7) * 15 + (dw + 7);
        float bv = bias_table[((size_t)l * 225 + rpi) * 8 + head];
        g_bp[(((size_t)l * 8 + head) * 64 + i) * 64 + j] = bv + 0.01f * __expf(-factor * dis);
    }
}

// ---------------------------------------------------------------------------
// attention per (window, head): 64 threads, thread i owns query row i.
// ---------------------------------------------------------------------------
__global__ void __launch_bounds__(64)
attn_kernel(const float* __restrict__ qkv, float* __restrict__ attns_out,
            float* __restrict__ obuf, int layer)
{
    const float SCALE = 0.17677669529663689f;  // 32^-0.5
    int head = blockIdx.x;
    int win  = blockIdx.y;
    int i    = threadIdx.x;

    __shared__ float ks[64][32];
    __shared__ float vs[64][32];

    const float* base = qkv + (size_t)win * 64 * 768 + head * 32;
    float q[32];
#pragma unroll
    for (int d = 0; d < 32; d++) q[d]      = base[(size_t)i * 768 + d];
#pragma unroll
    for (int d = 0; d < 32; d++) ks[i][d]  = base[(size_t)i * 768 + 256 + d];
#pragma unroll
    for (int d = 0; d < 32; d++) vs[i][d]  = base[(size_t)i * 768 + 512 + d];
    __syncthreads();

    float dots[64];
#pragma unroll 4
    for (int j = 0; j < 64; j++) {
        float s = 0.f;
#pragma unroll
        for (int d = 0; d < 32; d++) s += q[d] * ks[j][d];
        dots[j] = s * SCALE;
    }

    // softmax over raw dots (attns output)
    float m0 = -1e30f;
#pragma unroll
    for (int j = 0; j < 64; j++) m0 = fmaxf(m0, dots[j]);
    float sum0 = 0.f;
#pragma unroll
    for (int j = 0; j < 64; j++) sum0 += __expf(dots[j] - m0);
    float inv0 = 1.f / sum0;
    float* arow = attns_out + (((size_t)layer * NWIN + win) * 8 + head) * 4096 + (size_t)i * 64;
#pragma unroll
    for (int j = 0; j < 64; j++) arow[j] = __expf(dots[j] - m0) * inv0;

    // biased softmax
    const float* bp = g_bp + (((size_t)layer * 8 + head) * 64 + i) * 64;
#pragma unroll
    for (int j = 0; j < 64; j++) dots[j] += bp[j];
    float m1 = -1e30f;
#pragma unroll
    for (int j = 0; j < 64; j++) m1 = fmaxf(m1, dots[j]);
    float sum1 = 0.f;
#pragma unroll
    for (int j = 0; j < 64; j++) { dots[j] = __expf(dots[j] - m1); sum1 += dots[j]; }
    float inv1 = 1.f / sum1;

    float acc[32];
#pragma unroll
    for (int d = 0; d < 32; d++) acc[d] = 0.f;
#pragma unroll 4
    for (int j = 0; j < 64; j++) {
        float a = dots[j] * inv1;
#pragma unroll
        for (int d = 0; d < 32; d++) acc[d] += a * vs[j][d];
    }
    float* orow = obuf + (size_t)(win * 64 + i) * 256 + head * 32;
#pragma unroll
    for (int d = 0; d < 32; d++) orow[d] = acc[d];
}

// ---------------------------------------------------------------------------
extern "C" void kernel_launch(void* const* d_in, const int* in_sizes, int n_in,
                              void* d_out, int out_size)
{
    const float* x          = (const float*)d_in[0];
    const float* W_patch    = (const float*)d_in[1];
    const float* b_patch    = (const float*)d_in[2];
    const float* ln1_g      = (const float*)d_in[3];
    const float* ln1_b      = (const float*)d_in[4];
    const float* Wqkv       = (const float*)d_in[5];
    const float* headsita   = (const float*)d_in[6];
    const float* bias_table = (const float*)d_in[7];
    const float* Wout       = (const float*)d_in[8];
    const float* bout       = (const float*)d_in[9];
    const float* ln2_g      = (const float*)d_in[10];
    const float* ln2_b      = (const float*)d_in[11];
    const float* W1         = (const float*)d_in[12];
    const float* b1         = (const float*)d_in[13];
    const float* W2         = (const float*)d_in[14];
    const float* b2         = (const float*)d_in[15];

    float* out   = (float*)d_out;
    float* attns = out + (size_t)16777216;

    float *t, *h, *qkvb, *ob, *mlpb;
    cudaGetSymbolAddress((void**)&t,    g_t);
    cudaGetSymbolAddress((void**)&h,    g_h);
    cudaGetSymbolAddress((void**)&qkvb, g_qkv);
    cudaGetSymbolAddress((void**)&ob,   g_o);
    cudaGetSymbolAddress((void**)&mlpb, g_mlp);

    // raise dynamic smem limit for all GEMM instantiations (host-side, capture-safe)
    static bool attr_done = false;
    if (!attr_done) {
        cudaFuncSetAttribute(tgemm_kernel<true,  false, false>, cudaFuncAttributeMaxDynamicSharedMemorySize, GEMM_SMEM_BYTES);
        cudaFuncSetAttribute(tgemm_kernel<false, false, false>, cudaFuncAttributeMaxDynamicSharedMemorySize, GEMM_SMEM_BYTES);
        cudaFuncSetAttribute(tgemm_kernel<true,  false, true >, cudaFuncAttributeMaxDynamicSharedMemorySize, GEMM_SMEM_BYTES);
        cudaFuncSetAttribute(tgemm_kernel<true,  true,  false>, cudaFuncAttributeMaxDynamicSharedMemorySize, GEMM_SMEM_BYTES);
        attr_done = true;
    }

    dim3 tb32x8(32, 8);
    dim3 g_gather(4, 8, 512);

    gather_kernel<<<g_gather, tb32x8>>>(x, h);

    tgemm_kernel<true, false, false><<<dim3(2, 512), 256, GEMM_SMEM_BYTES>>>(h, W_patch, b_patch, nullptr, t, TOK, 256, 256);

    bp_kernel<<<dim3(8, 2), 64>>>(bias_table, headsita);

    for (int l = 0; l < 2; l++) {
        ln_kernel<<<8192, tb32x8>>>(t, ln1_g + l * 256, ln1_b + l * 256, h);
        tgemm_kernel<false, false, false><<<dim3(6, 512), 256, GEMM_SMEM_BYTES>>>(h, Wqkv + (size_t)l * 196608, nullptr, nullptr, qkvb, TOK, 768, 256);
        attn_kernel<<<dim3(8, NWIN), 64>>>(qkvb, attns, ob, l);
        tgemm_kernel<true, false, true><<<dim3(2, 512), 256, GEMM_SMEM_BYTES>>>(ob, Wout + (size_t)l * 65536, bout + l * 256, t, t, TOK, 256, 256);
        ln_kernel<<<8192, tb32x8>>>(t, ln2_g + l * 256, ln2_b + l * 256, h);
        tgemm_kernel<true, true, false><<<dim3(8, 512), 256, GEMM_SMEM_BYTES>>>(h, W1 + (size_t)l * 262144, b1 + l * 1024, nullptr, mlpb, TOK, 1024, 256);
        tgemm_kernel<true, false, true><<<dim3(2, 512), 256, GEMM_SMEM_BYTES>>>(mlpb, W2 + (size_t)l * 262144, b2 + l * 256, t, t, TOK, 256, 1024);
    }

    reverse_kernel<<<g_gather, tb32x8>>>(t, out);
}